// round 15
// baseline (speedup 1.0000x reference)
#include <cuda_runtime.h>
#include <cuda_fp16.h>

#define N_NODES 100000
#define NEDGES  1250000
#define D       64
#define H       8
#define NTILES  (N_NODES / 16)   // 6250
// DH = 8, scale = 1/sqrt(8)

// Scratch (static __device__ arrays: allocation-free per harness rules)
__device__ float g_Q[N_NODES * D];
__device__ float g_K[N_NODES * D];
__device__ float g_V[N_NODES * D];
__device__ float g_Z[N_NODES * H];

// ---------------------------------------------------------------------------
// helpers
// ---------------------------------------------------------------------------
__device__ __forceinline__ void red_add_v4(float* p, float x, float y, float z, float w) {
    asm volatile("red.global.add.v4.f32 [%0], {%1, %2, %3, %4};"
                 :: "l"(p), "f"(x), "f"(y), "f"(z), "f"(w) : "memory");
}

// split a float2 into hi/lo packed f16x2 (hi + lo recovers ~22 mantissa bits)
__device__ __forceinline__ void split_f16x2(float2 v, unsigned& h, unsigned& l) {
    __half2 hb = __floats2half2_rn(v.x, v.y);
    float2 hf = __half22float2(hb);
    __half2 lb = __floats2half2_rn(v.x - hf.x, v.y - hf.y);
    h = *reinterpret_cast<unsigned*>(&hb);
    l = *reinterpret_cast<unsigned*>(&lb);
}

__device__ __forceinline__ unsigned pack_f16x2(float a, float b) {
    __half2 hb = __floats2half2_rn(a, b);
    return *reinterpret_cast<unsigned*>(&hb);
}

// D += A(f16) * B(f16), m16n8k16, f32 accumulate
__device__ __forceinline__ void mma_f16(float* c, const unsigned* a,
                                        unsigned b0, unsigned b1) {
    asm volatile(
        "mma.sync.aligned.m16n8k16.row.col.f32.f16.f16.f32 "
        "{%0,%1,%2,%3}, {%4,%5,%6,%7}, {%8,%9}, {%0,%1,%2,%3};"
        : "+f"(c[0]), "+f"(c[1]), "+f"(c[2]), "+f"(c[3])
        : "r"(a[0]), "r"(a[1]), "r"(a[2]), "r"(a[3]), "r"(b0), "r"(b1));
}

// ---------------------------------------------------------------------------
// K1: QKV projections (round-14 verbatim). fp16-split 3-pass mma; coalesced
// two-stage weight staging; grid-stride tiles; zeroes out[] and g_Z.
// ---------------------------------------------------------------------------
__global__ __launch_bounds__(256) void proj_kernel(
    const float* __restrict__ x,
    const float* __restrict__ WQ,
    const float* __restrict__ WK,
    const float* __restrict__ WV,
    float* __restrict__ out)
{
    __shared__ uint4 sB[3][8][4][32];   // 48 KB

    const int tid = threadIdx.x;

    {
        float* raw1 = reinterpret_cast<float*>(&sB[1][0][0][0]);
        float* raw2 = reinterpret_cast<float*>(&sB[2][0][0][0]);

        for (int i = tid; i < 1024; i += 256)
            reinterpret_cast<float4*>(raw1)[i] = __ldg(&reinterpret_cast<const float4*>(WQ)[i]);
        __syncthreads();
        for (int t = tid; t < 1024; t += 256) {
            int n = t >> 7, k = (t >> 5) & 3, l = t & 31;
            int tig = l & 3, grp = l >> 2;
            int col = n * 8 + grp, r0 = k * 16 + 2 * tig;
            float2 w0 = make_float2(raw1[r0 * D + col],       raw1[(r0 + 1) * D + col]);
            float2 w1 = make_float2(raw1[(r0 + 8) * D + col], raw1[(r0 + 9) * D + col]);
            unsigned h0, l0, h1, l1;
            split_f16x2(w0, h0, l0);
            split_f16x2(w1, h1, l1);
            sB[0][n][k][l] = make_uint4(h0, h1, l0, l1);
        }
        __syncthreads();

        for (int i = tid; i < 1024; i += 256)
            reinterpret_cast<float4*>(raw2)[i] = __ldg(&reinterpret_cast<const float4*>(WK)[i]);
        __syncthreads();
        for (int t = tid; t < 1024; t += 256) {
            int n = t >> 7, k = (t >> 5) & 3, l = t & 31;
            int tig = l & 3, grp = l >> 2;
            int col = n * 8 + grp, r0 = k * 16 + 2 * tig;
            float2 w0 = make_float2(raw2[r0 * D + col],       raw2[(r0 + 1) * D + col]);
            float2 w1 = make_float2(raw2[(r0 + 8) * D + col], raw2[(r0 + 9) * D + col]);
            unsigned h0, l0, h1, l1;
            split_f16x2(w0, h0, l0);
            split_f16x2(w1, h1, l1);
            sB[1][n][k][l] = make_uint4(h0, h1, l0, l1);
        }
        __syncthreads();

        for (int i = tid; i < 1024; i += 256)
            reinterpret_cast<float4*>(raw2)[i] = __ldg(&reinterpret_cast<const float4*>(WV)[i]);
        __syncthreads();
        uint4 frag[4];
        int   fidx[4];
        for (int t = tid, j = 0; t < 1024; t += 256, j++) {
            int n = t >> 7, k = (t >> 5) & 3, l = t & 31;
            int tig = l & 3, grp = l >> 2;
            int col = n * 8 + grp, r0 = k * 16 + 2 * tig;
            float2 w0 = make_float2(raw2[r0 * D + col],       raw2[(r0 + 1) * D + col]);
            float2 w1 = make_float2(raw2[(r0 + 8) * D + col], raw2[(r0 + 9) * D + col]);
            unsigned h0, l0, h1, l1;
            split_f16x2(w0, h0, l0);
            split_f16x2(w1, h1, l1);
            frag[j] = make_uint4(h0, h1, l0, l1);
            fidx[j] = t;
        }
        __syncthreads();
#pragma unroll
        for (int j = 0; j < 4; j++) {
            int t = fidx[j];
            int n = t >> 7, k = (t >> 5) & 3, l = t & 31;
            sB[2][n][k][l] = frag[j];
        }
        __syncthreads();
    }

    const int warp = tid >> 5;
    const int lane = tid & 31;
    const int grp = lane >> 2;
    const int tig = lane & 3;

    float* Outs[3] = {g_Q, g_K, g_V};

    for (int tile = blockIdx.x * 8 + warp; tile < NTILES; tile += gridDim.x * 8) {
        const long row0 = (long)tile * 16 + grp;
        const long row1 = row0 + 8;

        unsigned Ah[4][4], Al[4][4];
#pragma unroll
        for (int k = 0; k < 4; k++) {
            float2 x0 = __ldg(reinterpret_cast<const float2*>(x + row0 * D + k * 16 + 2 * tig));
            float2 x1 = __ldg(reinterpret_cast<const float2*>(x + row1 * D + k * 16 + 2 * tig));
            float2 x2 = __ldg(reinterpret_cast<const float2*>(x + row0 * D + k * 16 + 8 + 2 * tig));
            float2 x3 = __ldg(reinterpret_cast<const float2*>(x + row1 * D + k * 16 + 8 + 2 * tig));
            split_f16x2(x0, Ah[k][0], Al[k][0]);
            split_f16x2(x1, Ah[k][1], Al[k][1]);
            split_f16x2(x2, Ah[k][2], Al[k][2]);
            split_f16x2(x3, Ah[k][3], Al[k][3]);
        }

#pragma unroll
        for (int w = 0; w < 3; w++) {
            float* O = Outs[w];
#pragma unroll
            for (int n = 0; n < 8; n++) {
                uint4 b[4];
#pragma unroll
                for (int k = 0; k < 4; k++) b[k] = sB[w][n][k][lane];

                float c1[4] = {0.f, 0.f, 0.f, 0.f};
                float c2[4] = {0.f, 0.f, 0.f, 0.f};
                float c3[4] = {0.f, 0.f, 0.f, 0.f};
#pragma unroll
                for (int k = 0; k < 4; k++) {
                    mma_f16(c1, Ah[k], b[k].x, b[k].y);   // hh
                    mma_f16(c2, Ah[k], b[k].z, b[k].w);   // h*l
                    mma_f16(c3, Al[k], b[k].x, b[k].y);   // l*h
                }

                int cc = n * 8 + 2 * tig;
                *reinterpret_cast<float2*>(&O[row0 * D + cc]) =
                    make_float2(c1[0] + c2[0] + c3[0], c1[1] + c2[1] + c3[1]);
                *reinterpret_cast<float2*>(&O[row1 * D + cc]) =
                    make_float2(c1[2] + c2[2] + c3[2], c1[3] + c2[3] + c3[3]);
            }
        }

        float4 z4 = make_float4(0.f, 0.f, 0.f, 0.f);
        float4* o4 = reinterpret_cast<float4*>(out) + (long)tile * 256;
#pragma unroll
        for (int i = 0; i < 8; i++) o4[i * 32 + lane] = z4;
        reinterpret_cast<float4*>(g_Z)[(long)tile * 32 + lane] = z4;
    }
}

// ---------------------------------------------------------------------------
// K2: FUSED edge kernel, WIDE phase B. Per warp = 16 edges.
//  Phase A (unchanged): Ef tile = ea[16x64] @ WE via fp16 2-pass split mma.
//  Phase B (NEW): 8 lanes per edge — lane g8=lane&7 owns cols 8g8..8g8+7 =
//    exactly head g8, so the score dot is lane-local (no shfl reduce).
//    Quarter-warp per edge -> 4 edges in flight, 4 iterations, uniform
//    depth-1 prefetch of all 6 gathers (2xK,2xQ,2xV float4). ~2x the
//    independent memory chains of the half-warp scheme at identical
//    LDG/REDG issue counts.
// NEDGES % 16 == 0 -> every live warp-tile is full.
// ---------------------------------------------------------------------------
__global__ __launch_bounds__(256) void fused_edge_kernel(
    const float* __restrict__ ea,
    const float* __restrict__ WE,
    const int* __restrict__ ei,
    float* __restrict__ out)
{
    __shared__ uint2 sB[8][4][32];     // 8 KB  (WE fp16 B-fragments)
    __shared__ float sEf[8][16][64];   // 32 KB (per-warp 16x64 Ef tiles)

    const int tid = threadIdx.x;

    for (int t = tid; t < 1024; t += 256) {
        int n = t >> 7, k = (t >> 5) & 3, l = t & 31;
        int tig = l & 3, grp = l >> 2;
        int col = n * 8 + grp;
        int r0 = k * 16 + 2 * tig;
        unsigned b0 = pack_f16x2(__ldg(&WE[r0 * D + col]),       __ldg(&WE[(r0 + 1) * D + col]));
        unsigned b1 = pack_f16x2(__ldg(&WE[(r0 + 8) * D + col]), __ldg(&WE[(r0 + 9) * D + col]));
        sB[n][k][l] = make_uint2(b0, b1);
    }
    __syncthreads();

    const int warp = tid >> 5;
    const int lane = tid & 31;
    const int base = (blockIdx.x * 8 + warp) * 16;
    if (base >= NEDGES) return;

    // edge indices: lanes 0-15 hold src, lanes 16-31 hold dst
    int sd = __ldg(&ei[(lane >> 4) * NEDGES + base + (lane & 15)]);

    const int q8 = lane >> 3;   // 0..3 — edge slot within iteration
    const int g8 = lane & 7;    // 0..7 — col group == head

    // --- issue iteration-0 gathers NOW (hidden under the mma loop) ---
    int s_c = __shfl_sync(0xFFFFFFFFu, sd, q8);
    int d_c = __shfl_sync(0xFFFFFFFFu, sd, 16 + q8);
    float4 ka = __ldg(reinterpret_cast<const float4*>(&g_K[(long)s_c * D + 8 * g8]));
    float4 kb = __ldg(reinterpret_cast<const float4*>(&g_K[(long)s_c * D + 8 * g8 + 4]));
    float4 qa = __ldg(reinterpret_cast<const float4*>(&g_Q[(long)d_c * D + 8 * g8]));
    float4 qb = __ldg(reinterpret_cast<const float4*>(&g_Q[(long)d_c * D + 8 * g8 + 4]));
    float4 va = __ldg(reinterpret_cast<const float4*>(&g_V[(long)s_c * D + 8 * g8]));
    float4 vb = __ldg(reinterpret_cast<const float4*>(&g_V[(long)s_c * D + 8 * g8 + 4]));

    const int grp = lane >> 2;    // 0..7  (phase-A row within tile)
    const int tig = lane & 3;     // 0..3  (phase-A col pair)
    const long row0 = base + grp;
    const long row1 = row0 + 8;

    // --- A fragments (16 x LDG.64, evict-first), fp16 hi/lo split ---
    unsigned Ah[4][4], Al[4][4];
#pragma unroll
    for (int k = 0; k < 4; k++) {
        float2 x0 = __ldcs(reinterpret_cast<const float2*>(ea + row0 * D + k * 16 + 2 * tig));
        float2 x1 = __ldcs(reinterpret_cast<const float2*>(ea + row1 * D + k * 16 + 2 * tig));
        float2 x2 = __ldcs(reinterpret_cast<const float2*>(ea + row0 * D + k * 16 + 8 + 2 * tig));
        float2 x3 = __ldcs(reinterpret_cast<const float2*>(ea + row1 * D + k * 16 + 8 + 2 * tig));
        split_f16x2(x0, Ah[k][0], Al[k][0]);
        split_f16x2(x1, Ah[k][1], Al[k][1]);
        split_f16x2(x2, Ah[k][2], Al[k][2]);
        split_f16x2(x3, Ah[k][3], Al[k][3]);
    }

    const int swz = (grp & 7) << 3;
#pragma unroll
    for (int n = 0; n < 8; n++) {
        uint2 b[4];
#pragma unroll
        for (int k = 0; k < 4; k++) b[k] = sB[n][k][lane];

        float c1[4] = {0.f, 0.f, 0.f, 0.f};
        float c2[4] = {0.f, 0.f, 0.f, 0.f};
#pragma unroll
        for (int k = 0; k < 4; k++) {
            mma_f16(c1, Ah[k], b[k].x, b[k].y);   // hi x W
            mma_f16(c2, Al[k], b[k].x, b[k].y);   // lo x W
        }

        int colw = (8 * n + 2 * tig) ^ swz;
        *reinterpret_cast<float2*>(&sEf[warp][grp][colw]) =
            make_float2(c1[0] + c2[0], c1[1] + c2[1]);
        *reinterpret_cast<float2*>(&sEf[warp][grp + 8][colw]) =
            make_float2(c1[2] + c2[2], c1[3] + c2[3]);
    }
    __syncwarp();

    // --- phase B: 4 iterations, 4 edges each, depth-1 prefetch ---
#pragma unroll
    for (int it = 0; it < 4; it++) {
        int s_n = 0, d_n = 0;
        float4 ka_n, kb_n, qa_n, qb_n, va_n, vb_n;
        if (it < 3) {
            s_n = __shfl_sync(0xFFFFFFFFu, sd, (it + 1) * 4 + q8);
            d_n = __shfl_sync(0xFFFFFFFFu, sd, 16 + (it + 1) * 4 + q8);
            ka_n = __ldg(reinterpret_cast<const float4*>(&g_K[(long)s_n * D + 8 * g8]));
            kb_n = __ldg(reinterpret_cast<const float4*>(&g_K[(long)s_n * D + 8 * g8 + 4]));
            qa_n = __ldg(reinterpret_cast<const float4*>(&g_Q[(long)d_n * D + 8 * g8]));
            qb_n = __ldg(reinterpret_cast<const float4*>(&g_Q[(long)d_n * D + 8 * g8 + 4]));
            va_n = __ldg(reinterpret_cast<const float4*>(&g_V[(long)s_n * D + 8 * g8]));
            vb_n = __ldg(reinterpret_cast<const float4*>(&g_V[(long)s_n * D + 8 * g8 + 4]));
        }

        int r = it * 4 + q8;
        const float4* efp = reinterpret_cast<const float4*>(
            &sEf[warp][r][(8 * g8) ^ ((r & 7) << 3)]);
        float4 e0 = efp[0];
        float4 e1 = efp[1];

        // lane-local 8-element score dot (whole head in this lane)
        float p = (ka.x * qa.x) * e0.x;
        p = fmaf(ka.y * qa.y, e0.y, p);
        p = fmaf(ka.z * qa.z, e0.z, p);
        p = fmaf(ka.w * qa.w, e0.w, p);
        p = fmaf(kb.x * qb.x, e1.x, p);
        p = fmaf(kb.y * qb.y, e1.y, p);
        p = fmaf(kb.z * qb.z, e1.z, p);
        p = fmaf(kb.w * qb.w, e1.w, p);

        // clamp in p-domain (+-5*sqrt(8)); exp(x/sqrt8)=2^(x*log2e/sqrt8)
        float sv = fminf(14.142135623730951f, fmaxf(-14.142135623730951f, p));
        float sc = exp2f(sv * 0.51002501915290554f);

        red_add_v4(&out[(long)d_c * D + 8 * g8],
                   va.x * sc, va.y * sc, va.z * sc, va.w * sc);
        red_add_v4(&out[(long)d_c * D + 8 * g8 + 4],
                   vb.x * sc, vb.y * sc, vb.z * sc, vb.w * sc);
        atomicAdd(&g_Z[d_c * H + g8], sc);

        ka = ka_n; kb = kb_n; qa = qa_n; qb = qb_n; va = va_n; vb = vb_n;
        s_c = s_n; d_c = d_n;
    }
}

// ---------------------------------------------------------------------------
// K3: out = wV / (Z + 1e-6)   (one float4 per thread)
// ---------------------------------------------------------------------------
__global__ void div_kernel(float4* __restrict__ out4) {
    int i = blockIdx.x * blockDim.x + threadIdx.x;
    if (i >= (N_NODES * D) / 4) return;
    int n  = i >> 4;
    int c4 = i & 15;
    int h  = c4 >> 1;
    float r = 1.0f / (g_Z[n * H + h] + 1e-6f);
    float4 v = out4[i];
    v.x *= r; v.y *= r; v.z *= r; v.w *= r;
    out4[i] = v;
}

// ---------------------------------------------------------------------------
extern "C" void kernel_launch(void* const* d_in, const int* in_sizes, int n_in,
                              void* d_out, int out_size)
{
    const float* x   = (const float*)d_in[0];
    const float* ea  = (const float*)d_in[1];
    const float* WQ  = (const float*)d_in[2];
    const float* WK  = (const float*)d_in[3];
    const float* WV  = (const float*)d_in[4];
    const float* WE  = (const float*)d_in[5];
    const int*   ei  = (const int*)d_in[6];
    float* out = (float*)d_out;

    (void)in_sizes; (void)n_in; (void)out_size;

    proj_kernel<<<391, 256>>>(x, WQ, WK, WV, out);
    fused_edge_kernel<<<(NEDGES / 16 + 7) / 8, 256>>>(ea, WE, ei, out);
    div_kernel<<<(N_NODES * D / 4 + 255) / 256, 256>>>((float4*)out);
}

// round 16
// speedup vs baseline: 1.1839x; 1.1839x over previous
#include <cuda_runtime.h>
#include <cuda_fp16.h>

#define N_NODES 100000
#define NEDGES  1250000
#define D       64
#define H       8
#define NTILES  (N_NODES / 16)   // 6250
// DH = 8, scale = 1/sqrt(8)

// Scratch (static __device__ arrays: allocation-free per harness rules)
__device__ float g_Q[N_NODES * D];
__device__ float g_K[N_NODES * D];
__device__ float g_V[N_NODES * D];
__device__ float g_Z[N_NODES * H];

// ---------------------------------------------------------------------------
// helpers
// ---------------------------------------------------------------------------
__device__ __forceinline__ void red_add_v4(float* p, float x, float y, float z, float w) {
    asm volatile("red.global.add.v4.f32 [%0], {%1, %2, %3, %4};"
                 :: "l"(p), "f"(x), "f"(y), "f"(z), "f"(w) : "memory");
}

// split a float2 into hi/lo packed f16x2 (hi + lo recovers ~22 mantissa bits)
__device__ __forceinline__ void split_f16x2(float2 v, unsigned& h, unsigned& l) {
    __half2 hb = __floats2half2_rn(v.x, v.y);
    float2 hf = __half22float2(hb);
    __half2 lb = __floats2half2_rn(v.x - hf.x, v.y - hf.y);
    h = *reinterpret_cast<unsigned*>(&hb);
    l = *reinterpret_cast<unsigned*>(&lb);
}

__device__ __forceinline__ unsigned pack_f16x2(float a, float b) {
    __half2 hb = __floats2half2_rn(a, b);
    return *reinterpret_cast<unsigned*>(&hb);
}

// D += A(f16) * B(f16), m16n8k16, f32 accumulate
__device__ __forceinline__ void mma_f16(float* c, const unsigned* a,
                                        unsigned b0, unsigned b1) {
    asm volatile(
        "mma.sync.aligned.m16n8k16.row.col.f32.f16.f16.f32 "
        "{%0,%1,%2,%3}, {%4,%5,%6,%7}, {%8,%9}, {%0,%1,%2,%3};"
        : "+f"(c[0]), "+f"(c[1]), "+f"(c[2]), "+f"(c[3])
        : "r"(a[0]), "r"(a[1]), "r"(a[2]), "r"(a[3]), "r"(b0), "r"(b1));
}

// ---------------------------------------------------------------------------
// K1: QKV projections via fp16-split tensor-core mma, 3-pass (hh + hl + lh).
// Grid-stride over 16-node tiles (2 tiles/warp at grid=391, single wave).
// Weight staging is COALESCED: raw W -> SMEM via float4 LDG, fragments built
// from SMEM via LDS. Raw mats ping-pong through not-yet-built sB regions so
// static SMEM stays at 48 KB. Also zeroes out[] rows and g_Z rows.
// ---------------------------------------------------------------------------
__global__ __launch_bounds__(256) void proj_kernel(
    const float* __restrict__ x,
    const float* __restrict__ WQ,
    const float* __restrict__ WK,
    const float* __restrict__ WV,
    float* __restrict__ out)
{
    // [mat][ntile][kstep][lane] = (bh0, bh1, bl0, bl1)
    __shared__ uint4 sB[3][8][4][32];   // 48 KB

    const int tid = threadIdx.x;

    // ---- coalesced staging + fragment build ----
    {
        float* raw1 = reinterpret_cast<float*>(&sB[1][0][0][0]);
        float* raw2 = reinterpret_cast<float*>(&sB[2][0][0][0]);

        // mat 0: raw WQ -> sB[1] region, build frags -> sB[0]
        for (int i = tid; i < 1024; i += 256)
            reinterpret_cast<float4*>(raw1)[i] = __ldg(&reinterpret_cast<const float4*>(WQ)[i]);
        __syncthreads();
        for (int t = tid; t < 1024; t += 256) {
            int n = t >> 7, k = (t >> 5) & 3, l = t & 31;
            int tig = l & 3, grp = l >> 2;
            int col = n * 8 + grp, r0 = k * 16 + 2 * tig;
            float2 w0 = make_float2(raw1[r0 * D + col],       raw1[(r0 + 1) * D + col]);
            float2 w1 = make_float2(raw1[(r0 + 8) * D + col], raw1[(r0 + 9) * D + col]);
            unsigned h0, l0, h1, l1;
            split_f16x2(w0, h0, l0);
            split_f16x2(w1, h1, l1);
            sB[0][n][k][l] = make_uint4(h0, h1, l0, l1);
        }
        __syncthreads();

        // mat 1: raw WK -> sB[2] region, build frags -> sB[1]
        for (int i = tid; i < 1024; i += 256)
            reinterpret_cast<float4*>(raw2)[i] = __ldg(&reinterpret_cast<const float4*>(WK)[i]);
        __syncthreads();
        for (int t = tid; t < 1024; t += 256) {
            int n = t >> 7, k = (t >> 5) & 3, l = t & 31;
            int tig = l & 3, grp = l >> 2;
            int col = n * 8 + grp, r0 = k * 16 + 2 * tig;
            float2 w0 = make_float2(raw2[r0 * D + col],       raw2[(r0 + 1) * D + col]);
            float2 w1 = make_float2(raw2[(r0 + 8) * D + col], raw2[(r0 + 9) * D + col]);
            unsigned h0, l0, h1, l1;
            split_f16x2(w0, h0, l0);
            split_f16x2(w1, h1, l1);
            sB[1][n][k][l] = make_uint4(h0, h1, l0, l1);
        }
        __syncthreads();

        // mat 2: raw WV -> sB[2] region (overwrites dead raw WK), then
        // in-place build: read raw into registers, sync, write frags.
        for (int i = tid; i < 1024; i += 256)
            reinterpret_cast<float4*>(raw2)[i] = __ldg(&reinterpret_cast<const float4*>(WV)[i]);
        __syncthreads();
        uint4 frag[4];
        int   fidx[4];
        for (int t = tid, j = 0; t < 1024; t += 256, j++) {
            int n = t >> 7, k = (t >> 5) & 3, l = t & 31;
            int tig = l & 3, grp = l >> 2;
            int col = n * 8 + grp, r0 = k * 16 + 2 * tig;
            float2 w0 = make_float2(raw2[r0 * D + col],       raw2[(r0 + 1) * D + col]);
            float2 w1 = make_float2(raw2[(r0 + 8) * D + col], raw2[(r0 + 9) * D + col]);
            unsigned h0, l0, h1, l1;
            split_f16x2(w0, h0, l0);
            split_f16x2(w1, h1, l1);
            frag[j] = make_uint4(h0, h1, l0, l1);
            fidx[j] = t;
        }
        __syncthreads();
#pragma unroll
        for (int j = 0; j < 4; j++) {
            int t = fidx[j];
            int n = t >> 7, k = (t >> 5) & 3, l = t & 31;
            sB[2][n][k][l] = frag[j];
        }
        __syncthreads();
    }

    const int warp = tid >> 5;
    const int lane = tid & 31;
    const int grp = lane >> 2;
    const int tig = lane & 3;

    float* Outs[3] = {g_Q, g_K, g_V};

    for (int tile = blockIdx.x * 8 + warp; tile < NTILES; tile += gridDim.x * 8) {
        const long row0 = (long)tile * 16 + grp;
        const long row1 = row0 + 8;

        // --- A fragments from x (hi/lo fp16 split) ---
        unsigned Ah[4][4], Al[4][4];
#pragma unroll
        for (int k = 0; k < 4; k++) {
            float2 x0 = __ldg(reinterpret_cast<const float2*>(x + row0 * D + k * 16 + 2 * tig));
            float2 x1 = __ldg(reinterpret_cast<const float2*>(x + row1 * D + k * 16 + 2 * tig));
            float2 x2 = __ldg(reinterpret_cast<const float2*>(x + row0 * D + k * 16 + 8 + 2 * tig));
            float2 x3 = __ldg(reinterpret_cast<const float2*>(x + row1 * D + k * 16 + 8 + 2 * tig));
            split_f16x2(x0, Ah[k][0], Al[k][0]);
            split_f16x2(x1, Ah[k][1], Al[k][1]);
            split_f16x2(x2, Ah[k][2], Al[k][2]);
            split_f16x2(x3, Ah[k][3], Al[k][3]);
        }

#pragma unroll
        for (int w = 0; w < 3; w++) {
            float* O = Outs[w];
#pragma unroll
            for (int n = 0; n < 8; n++) {
                uint4 b[4];
#pragma unroll
                for (int k = 0; k < 4; k++) b[k] = sB[w][n][k][lane];

                float c1[4] = {0.f, 0.f, 0.f, 0.f};
                float c2[4] = {0.f, 0.f, 0.f, 0.f};
                float c3[4] = {0.f, 0.f, 0.f, 0.f};
#pragma unroll
                for (int k = 0; k < 4; k++) {
                    mma_f16(c1, Ah[k], b[k].x, b[k].y);   // hh
                    mma_f16(c2, Ah[k], b[k].z, b[k].w);   // h*l
                    mma_f16(c3, Al[k], b[k].x, b[k].y);   // l*h
                }

                int cc = n * 8 + 2 * tig;
                *reinterpret_cast<float2*>(&O[row0 * D + cc]) =
                    make_float2(c1[0] + c2[0] + c3[0], c1[1] + c2[1] + c3[1]);
                *reinterpret_cast<float2*>(&O[row1 * D + cc]) =
                    make_float2(c1[2] + c2[2] + c3[2], c1[3] + c2[3] + c3[3]);
            }
        }

        // --- zero accumulators for these 16 nodes ---
        float4 z4 = make_float4(0.f, 0.f, 0.f, 0.f);
        float4* o4 = reinterpret_cast<float4*>(out) + (long)tile * 256;
#pragma unroll
        for (int i = 0; i < 8; i++) o4[i * 32 + lane] = z4;
        reinterpret_cast<float4*>(g_Z)[(long)tile * 32 + lane] = z4;
    }
}

// ---------------------------------------------------------------------------
// K2: FUSED edge kernel (round-8 structure — measured best across six
// structural variants). Per warp = 16 edges.
//  Phase A: Ef tile = ea[16x64] @ WE via fp16 2-pass split mma
//           ((Ah + Al) x fp16(WE)), 64 m16n8k16 per warp-tile -> SMEM;
//           edge-0/1 K/Q/V gathers issued before the mma loop.
//  Phase B: 16 lanes/edge, depth-2 (kk/qq) + depth-1 (vv) software
//           pipeline, red.add.v4 scatter + Z atomic.
// NEDGES % 16 == 0 -> every live warp-tile is full.
// ---------------------------------------------------------------------------
__global__ __launch_bounds__(256) void fused_edge_kernel(
    const float* __restrict__ ea,
    const float* __restrict__ WE,
    const int* __restrict__ ei,
    float* __restrict__ out)
{
    __shared__ uint2 sB[8][4][32];     // 8 KB  (WE fp16 B-fragments)
    __shared__ float sEf[8][16][64];   // 32 KB (per-warp 16x64 Ef tiles)

    const int tid = threadIdx.x;

    for (int t = tid; t < 1024; t += 256) {
        int n = t >> 7, k = (t >> 5) & 3, l = t & 31;
        int tig = l & 3, grp = l >> 2;
        int col = n * 8 + grp;
        int r0 = k * 16 + 2 * tig;
        unsigned b0 = pack_f16x2(__ldg(&WE[r0 * D + col]),       __ldg(&WE[(r0 + 1) * D + col]));
        unsigned b1 = pack_f16x2(__ldg(&WE[(r0 + 8) * D + col]), __ldg(&WE[(r0 + 9) * D + col]));
        sB[n][k][l] = make_uint2(b0, b1);
    }
    __syncthreads();

    const int warp = tid >> 5;
    const int lane = tid & 31;
    const int base = (blockIdx.x * 8 + warp) * 16;
    if (base >= NEDGES) return;

    int sd = __ldg(&ei[(lane >> 4) * NEDGES + base + (lane & 15)]);

    const int half = lane >> 4;
    const int g    = lane & 15;

    int s0 = __shfl_sync(0xFFFFFFFFu, sd, half);
    int d0 = __shfl_sync(0xFFFFFFFFu, sd, 16 + half);
    int s1 = __shfl_sync(0xFFFFFFFFu, sd, 2 + half);
    int d1 = __shfl_sync(0xFFFFFFFFu, sd, 18 + half);
    float4 kk0 = __ldg(reinterpret_cast<const float4*>(&g_K[(long)s0 * D + 4 * g]));
    float4 qq0 = __ldg(reinterpret_cast<const float4*>(&g_Q[(long)d0 * D + 4 * g]));
    float4 vv0 = __ldg(reinterpret_cast<const float4*>(&g_V[(long)s0 * D + 4 * g]));
    float4 kk1 = __ldg(reinterpret_cast<const float4*>(&g_K[(long)s1 * D + 4 * g]));
    float4 qq1 = __ldg(reinterpret_cast<const float4*>(&g_Q[(long)d1 * D + 4 * g]));

    const int grp = lane >> 2;
    const int tig = lane & 3;
    const long row0 = base + grp;
    const long row1 = row0 + 8;

    unsigned Ah[4][4], Al[4][4];
#pragma unroll
    for (int k = 0; k < 4; k++) {
        float2 x0 = __ldcs(reinterpret_cast<const float2*>(ea + row0 * D + k * 16 + 2 * tig));
        float2 x1 = __ldcs(reinterpret_cast<const float2*>(ea + row1 * D + k * 16 + 2 * tig));
        float2 x2 = __ldcs(reinterpret_cast<const float2*>(ea + row0 * D + k * 16 + 8 + 2 * tig));
        float2 x3 = __ldcs(reinterpret_cast<const float2*>(ea + row1 * D + k * 16 + 8 + 2 * tig));
        split_f16x2(x0, Ah[k][0], Al[k][0]);
        split_f16x2(x1, Ah[k][1], Al[k][1]);
        split_f16x2(x2, Ah[k][2], Al[k][2]);
        split_f16x2(x3, Ah[k][3], Al[k][3]);
    }

    const int swz = (grp & 7) << 3;
#pragma unroll
    for (int n = 0; n < 8; n++) {
        uint2 b[4];
#pragma unroll
        for (int k = 0; k < 4; k++) b[k] = sB[n][k][lane];

        float c1[4] = {0.f, 0.f, 0.f, 0.f};
        float c2[4] = {0.f, 0.f, 0.f, 0.f};
#pragma unroll
        for (int k = 0; k < 4; k++) {
            mma_f16(c1, Ah[k], b[k].x, b[k].y);
            mma_f16(c2, Al[k], b[k].x, b[k].y);
        }

        int colw = (8 * n + 2 * tig) ^ swz;
        *reinterpret_cast<float2*>(&sEf[warp][grp][colw]) =
            make_float2(c1[0] + c2[0], c1[1] + c2[1]);
        *reinterpret_cast<float2*>(&sEf[warp][grp + 8][colw]) =
            make_float2(c1[2] + c2[2], c1[3] + c2[3]);
    }
    __syncwarp();

    int s2, d2;
    float4 kk2, qq2, vv1;
#pragma unroll
    for (int it = 0; it < 8; it++) {
        if (it < 7)
            vv1 = __ldg(reinterpret_cast<const float4*>(&g_V[(long)s1 * D + 4 * g]));
        if (it < 6) {
            s2 = __shfl_sync(0xFFFFFFFFu, sd, (it + 2) * 2 + half);
            d2 = __shfl_sync(0xFFFFFFFFu, sd, 16 + (it + 2) * 2 + half);
            kk2 = __ldg(reinterpret_cast<const float4*>(&g_K[(long)s2 * D + 4 * g]));
            qq2 = __ldg(reinterpret_cast<const float4*>(&g_Q[(long)d2 * D + 4 * g]));
        }

        int r = it * 2 + half;
        float4 ef = *reinterpret_cast<const float4*>(
            &sEf[warp][r][(4 * g) ^ ((r & 7) << 3)]);

        float p = (kk0.x * qq0.x) * ef.x;
        p = fmaf(kk0.y * qq0.y, ef.y, p);
        p = fmaf(kk0.z * qq0.z, ef.z, p);
        p = fmaf(kk0.w * qq0.w, ef.w, p);
        p += __shfl_xor_sync(0xFFFFFFFFu, p, 1);

        // clamp in p-domain (+-5*sqrt(8)); exp(x/sqrt8)=2^(x*log2e/sqrt8)
        float sv = fminf(14.142135623730951f, fmaxf(-14.142135623730951f, p));
        float sc = exp2f(sv * 0.51002501915290554f);

        red_add_v4(&out[(long)d0 * D + 4 * g],
                   vv0.x * sc, vv0.y * sc, vv0.z * sc, vv0.w * sc);
        if ((g & 1) == 0)
            atomicAdd(&g_Z[d0 * H + (g >> 1)], sc);

        kk0 = kk1; qq0 = qq1; vv0 = vv1; s0 = s1; d0 = d1;
        kk1 = kk2; qq1 = qq2; s1 = s2; d1 = d2;
    }
}

// ---------------------------------------------------------------------------
// K3: out = wV / (Z + 1e-6)   (one float4 per thread)
// ---------------------------------------------------------------------------
__global__ void div_kernel(float4* __restrict__ out4) {
    int i = blockIdx.x * blockDim.x + threadIdx.x;
    if (i >= (N_NODES * D) / 4) return;
    int n  = i >> 4;
    int c4 = i & 15;
    int h  = c4 >> 1;
    float r = 1.0f / (g_Z[n * H + h] + 1e-6f);
    float4 v = out4[i];
    v.x *= r; v.y *= r; v.z *= r; v.w *= r;
    out4[i] = v;
}

// ---------------------------------------------------------------------------
extern "C" void kernel_launch(void* const* d_in, const int* in_sizes, int n_in,
                              void* d_out, int out_size)
{
    const float* x   = (const float*)d_in[0];
    const float* ea  = (const float*)d_in[1];
    const float* WQ  = (const float*)d_in[2];
    const float* WK  = (const float*)d_in[3];
    const float* WV  = (const float*)d_in[4];
    const float* WE  = (const float*)d_in[5];
    const int*   ei  = (const int*)d_in[6];
    float* out = (float*)d_out;

    (void)in_sizes; (void)n_in; (void)out_size;

    proj_kernel<<<391, 256>>>(x, WQ, WK, WV, out);
    fused_edge_kernel<<<(NEDGES / 16 + 7) / 8, 256>>>(ea, WE, ei, out);
    div_kernel<<<(N_NODES * D / 4 + 255) / 256, 256>>>((float4*)out);
}

// round 17
// speedup vs baseline: 1.2433x; 1.0502x over previous
#include <cuda_runtime.h>
#include <cuda_fp16.h>

#define N_NODES 100000
#define NEDGES  1250000
#define D       64
#define H       8
#define NTILES  (N_NODES / 16)   // 6250
// DH = 8, scale = 1/sqrt(8)

// Scratch (static __device__ arrays: allocation-free per harness rules)
// K and Q stored as packed fp16 (32 x half2 per node); V stays fp32.
__device__ __half2 g_Kh[N_NODES * 32];
__device__ __half2 g_Qh[N_NODES * 32];
__device__ float   g_V[N_NODES * D];
__device__ float   g_Z[N_NODES * H];

// ---------------------------------------------------------------------------
// helpers
// ---------------------------------------------------------------------------
__device__ __forceinline__ void red_add_v4(float* p, float x, float y, float z, float w) {
    asm volatile("red.global.add.v4.f32 [%0], {%1, %2, %3, %4};"
                 :: "l"(p), "f"(x), "f"(y), "f"(z), "f"(w) : "memory");
}

// split a float2 into hi/lo packed f16x2 (hi + lo recovers ~22 mantissa bits)
__device__ __forceinline__ void split_f16x2(float2 v, unsigned& h, unsigned& l) {
    __half2 hb = __floats2half2_rn(v.x, v.y);
    float2 hf = __half22float2(hb);
    __half2 lb = __floats2half2_rn(v.x - hf.x, v.y - hf.y);
    h = *reinterpret_cast<unsigned*>(&hb);
    l = *reinterpret_cast<unsigned*>(&lb);
}

__device__ __forceinline__ unsigned pack_f16x2(float a, float b) {
    __half2 hb = __floats2half2_rn(a, b);
    return *reinterpret_cast<unsigned*>(&hb);
}

__device__ __forceinline__ float2 h2f(unsigned u) {
    __half2 h = *reinterpret_cast<__half2*>(&u);
    return __half22float2(h);
}

// D += A(f16) * B(f16), m16n8k16, f32 accumulate
__device__ __forceinline__ void mma_f16(float* c, const unsigned* a,
                                        unsigned b0, unsigned b1) {
    asm volatile(
        "mma.sync.aligned.m16n8k16.row.col.f32.f16.f16.f32 "
        "{%0,%1,%2,%3}, {%4,%5,%6,%7}, {%8,%9}, {%0,%1,%2,%3};"
        : "+f"(c[0]), "+f"(c[1]), "+f"(c[2]), "+f"(c[3])
        : "r"(a[0]), "r"(a[1]), "r"(a[2]), "r"(a[3]), "r"(b0), "r"(b1));
}

// ---------------------------------------------------------------------------
// K1: QKV projections via fp16-split tensor-core mma, 3-pass (hh + hl + lh).
// Q and K written as packed fp16 rows; V written fp32. Grid-stride tiles,
// coalesced two-stage weight staging. Also zeroes out[] rows and g_Z rows.
// ---------------------------------------------------------------------------
__global__ __launch_bounds__(256) void proj_kernel(
    const float* __restrict__ x,
    const float* __restrict__ WQ,
    const float* __restrict__ WK,
    const float* __restrict__ WV,
    float* __restrict__ out)
{
    // [mat][ntile][kstep][lane] = (bh0, bh1, bl0, bl1)
    __shared__ uint4 sB[3][8][4][32];   // 48 KB

    const int tid = threadIdx.x;

    // ---- coalesced staging + fragment build ----
    {
        float* raw1 = reinterpret_cast<float*>(&sB[1][0][0][0]);
        float* raw2 = reinterpret_cast<float*>(&sB[2][0][0][0]);

        // mat 0: raw WQ -> sB[1] region, build frags -> sB[0]
        for (int i = tid; i < 1024; i += 256)
            reinterpret_cast<float4*>(raw1)[i] = __ldg(&reinterpret_cast<const float4*>(WQ)[i]);
        __syncthreads();
        for (int t = tid; t < 1024; t += 256) {
            int n = t >> 7, k = (t >> 5) & 3, l = t & 31;
            int tig = l & 3, grp = l >> 2;
            int col = n * 8 + grp, r0 = k * 16 + 2 * tig;
            float2 w0 = make_float2(raw1[r0 * D + col],       raw1[(r0 + 1) * D + col]);
            float2 w1 = make_float2(raw1[(r0 + 8) * D + col], raw1[(r0 + 9) * D + col]);
            unsigned h0, l0, h1, l1;
            split_f16x2(w0, h0, l0);
            split_f16x2(w1, h1, l1);
            sB[0][n][k][l] = make_uint4(h0, h1, l0, l1);
        }
        __syncthreads();

        // mat 1: raw WK -> sB[2] region, build frags -> sB[1]
        for (int i = tid; i < 1024; i += 256)
            reinterpret_cast<float4*>(raw2)[i] = __ldg(&reinterpret_cast<const float4*>(WK)[i]);
        __syncthreads();
        for (int t = tid; t < 1024; t += 256) {
            int n = t >> 7, k = (t >> 5) & 3, l = t & 31;
            int tig = l & 3, grp = l >> 2;
            int col = n * 8 + grp, r0 = k * 16 + 2 * tig;
            float2 w0 = make_float2(raw2[r0 * D + col],       raw2[(r0 + 1) * D + col]);
            float2 w1 = make_float2(raw2[(r0 + 8) * D + col], raw2[(r0 + 9) * D + col]);
            unsigned h0, l0, h1, l1;
            split_f16x2(w0, h0, l0);
            split_f16x2(w1, h1, l1);
            sB[1][n][k][l] = make_uint4(h0, h1, l0, l1);
        }
        __syncthreads();

        // mat 2: raw WV -> sB[2] region, in-place build via registers
        for (int i = tid; i < 1024; i += 256)
            reinterpret_cast<float4*>(raw2)[i] = __ldg(&reinterpret_cast<const float4*>(WV)[i]);
        __syncthreads();
        uint4 frag[4];
        int   fidx[4];
        for (int t = tid, j = 0; t < 1024; t += 256, j++) {
            int n = t >> 7, k = (t >> 5) & 3, l = t & 31;
            int tig = l & 3, grp = l >> 2;
            int col = n * 8 + grp, r0 = k * 16 + 2 * tig;
            float2 w0 = make_float2(raw2[r0 * D + col],       raw2[(r0 + 1) * D + col]);
            float2 w1 = make_float2(raw2[(r0 + 8) * D + col], raw2[(r0 + 9) * D + col]);
            unsigned h0, l0, h1, l1;
            split_f16x2(w0, h0, l0);
            split_f16x2(w1, h1, l1);
            frag[j] = make_uint4(h0, h1, l0, l1);
            fidx[j] = t;
        }
        __syncthreads();
#pragma unroll
        for (int j = 0; j < 4; j++) {
            int t = fidx[j];
            int n = t >> 7, k = (t >> 5) & 3, l = t & 31;
            sB[2][n][k][l] = frag[j];
        }
        __syncthreads();
    }

    const int warp = tid >> 5;
    const int lane = tid & 31;
    const int grp = lane >> 2;
    const int tig = lane & 3;

    for (int tile = blockIdx.x * 8 + warp; tile < NTILES; tile += gridDim.x * 8) {
        const long row0 = (long)tile * 16 + grp;
        const long row1 = row0 + 8;

        // --- A fragments from x (hi/lo fp16 split) ---
        unsigned Ah[4][4], Al[4][4];
#pragma unroll
        for (int k = 0; k < 4; k++) {
            float2 x0 = __ldg(reinterpret_cast<const float2*>(x + row0 * D + k * 16 + 2 * tig));
            float2 x1 = __ldg(reinterpret_cast<const float2*>(x + row1 * D + k * 16 + 2 * tig));
            float2 x2 = __ldg(reinterpret_cast<const float2*>(x + row0 * D + k * 16 + 8 + 2 * tig));
            float2 x3 = __ldg(reinterpret_cast<const float2*>(x + row1 * D + k * 16 + 8 + 2 * tig));
            split_f16x2(x0, Ah[k][0], Al[k][0]);
            split_f16x2(x1, Ah[k][1], Al[k][1]);
            split_f16x2(x2, Ah[k][2], Al[k][2]);
            split_f16x2(x3, Ah[k][3], Al[k][3]);
        }

#pragma unroll
        for (int w = 0; w < 3; w++) {
#pragma unroll
            for (int n = 0; n < 8; n++) {
                uint4 b[4];
#pragma unroll
                for (int k = 0; k < 4; k++) b[k] = sB[w][n][k][lane];

                float c1[4] = {0.f, 0.f, 0.f, 0.f};
                float c2[4] = {0.f, 0.f, 0.f, 0.f};
                float c3[4] = {0.f, 0.f, 0.f, 0.f};
#pragma unroll
                for (int k = 0; k < 4; k++) {
                    mma_f16(c1, Ah[k], b[k].x, b[k].y);   // hh
                    mma_f16(c2, Ah[k], b[k].z, b[k].w);   // h*l
                    mma_f16(c3, Al[k], b[k].x, b[k].y);   // l*h
                }

                float r0a = c1[0] + c2[0] + c3[0], r0b = c1[1] + c2[1] + c3[1];
                float r1a = c1[2] + c2[2] + c3[2], r1b = c1[3] + c2[3] + c3[3];

                if (w == 2) {
                    int cc = n * 8 + 2 * tig;
                    *reinterpret_cast<float2*>(&g_V[row0 * D + cc]) = make_float2(r0a, r0b);
                    *reinterpret_cast<float2*>(&g_V[row1 * D + cc]) = make_float2(r1a, r1b);
                } else {
                    __half2* Oh = (w == 0) ? g_Qh : g_Kh;
                    int ch = n * 4 + tig;   // half2 index of col pair (cc/2)
                    Oh[row0 * 32 + ch] = __floats2half2_rn(r0a, r0b);
                    Oh[row1 * 32 + ch] = __floats2half2_rn(r1a, r1b);
                }
            }
        }

        // --- zero accumulators for these 16 nodes ---
        float4 z4 = make_float4(0.f, 0.f, 0.f, 0.f);
        float4* o4 = reinterpret_cast<float4*>(out) + (long)tile * 256;
#pragma unroll
        for (int i = 0; i < 8; i++) o4[i * 32 + lane] = z4;
        reinterpret_cast<float4*>(g_Z)[(long)tile * 32 + lane] = z4;
    }
}

// ---------------------------------------------------------------------------
// K2: FUSED edge kernel (round-8 structure; K/Q gathered as fp16 — halves
// gather traffic and pipeline registers). Per warp = 16 edges.
//  Phase A: Ef tile = ea[16x64] @ WE via fp16 2-pass split mma -> SMEM;
//           edge-0/1 gathers issued before the mma loop.
//  Phase B: 16 lanes/edge, depth-2 (K/Q) + depth-1 (V) software pipeline,
//           red.add.v4 scatter + Z atomic.
// NEDGES % 16 == 0 -> every live warp-tile is full.
// ---------------------------------------------------------------------------
__global__ __launch_bounds__(256) void fused_edge_kernel(
    const float* __restrict__ ea,
    const float* __restrict__ WE,
    const int* __restrict__ ei,
    float* __restrict__ out)
{
    __shared__ uint2 sB[8][4][32];     // 8 KB  (WE fp16 B-fragments)
    __shared__ float sEf[8][16][64];   // 32 KB (per-warp 16x64 Ef tiles)

    const int tid = threadIdx.x;

    for (int t = tid; t < 1024; t += 256) {
        int n = t >> 7, k = (t >> 5) & 3, l = t & 31;
        int tig = l & 3, grp = l >> 2;
        int col = n * 8 + grp;
        int r0 = k * 16 + 2 * tig;
        unsigned b0 = pack_f16x2(__ldg(&WE[r0 * D + col]),       __ldg(&WE[(r0 + 1) * D + col]));
        unsigned b1 = pack_f16x2(__ldg(&WE[(r0 + 8) * D + col]), __ldg(&WE[(r0 + 9) * D + col]));
        sB[n][k][l] = make_uint2(b0, b1);
    }
    __syncthreads();

    const int warp = tid >> 5;
    const int lane = tid & 31;
    const int base = (blockIdx.x * 8 + warp) * 16;
    if (base >= NEDGES) return;

    int sd = __ldg(&ei[(lane >> 4) * NEDGES + base + (lane & 15)]);

    const int half = lane >> 4;
    const int g    = lane & 15;

    int s0 = __shfl_sync(0xFFFFFFFFu, sd, half);
    int d0 = __shfl_sync(0xFFFFFFFFu, sd, 16 + half);
    int s1 = __shfl_sync(0xFFFFFFFFu, sd, 2 + half);
    int d1 = __shfl_sync(0xFFFFFFFFu, sd, 18 + half);
    // fp16 K/Q: lane g loads 4 halves (uint2) at half2 index 2g
    uint2 kk0 = *reinterpret_cast<const uint2*>(&g_Kh[(long)s0 * 32 + 2 * g]);
    uint2 qq0 = *reinterpret_cast<const uint2*>(&g_Qh[(long)d0 * 32 + 2 * g]);
    float4 vv0 = __ldg(reinterpret_cast<const float4*>(&g_V[(long)s0 * D + 4 * g]));
    uint2 kk1 = *reinterpret_cast<const uint2*>(&g_Kh[(long)s1 * 32 + 2 * g]);
    uint2 qq1 = *reinterpret_cast<const uint2*>(&g_Qh[(long)d1 * 32 + 2 * g]);

    const int grp = lane >> 2;
    const int tig = lane & 3;
    const long row0 = base + grp;
    const long row1 = row0 + 8;

    unsigned Ah[4][4], Al[4][4];
#pragma unroll
    for (int k = 0; k < 4; k++) {
        float2 x0 = __ldcs(reinterpret_cast<const float2*>(ea + row0 * D + k * 16 + 2 * tig));
        float2 x1 = __ldcs(reinterpret_cast<const float2*>(ea + row1 * D + k * 16 + 2 * tig));
        float2 x2 = __ldcs(reinterpret_cast<const float2*>(ea + row0 * D + k * 16 + 8 + 2 * tig));
        float2 x3 = __ldcs(reinterpret_cast<const float2*>(ea + row1 * D + k * 16 + 8 + 2 * tig));
        split_f16x2(x0, Ah[k][0], Al[k][0]);
        split_f16x2(x1, Ah[k][1], Al[k][1]);
        split_f16x2(x2, Ah[k][2], Al[k][2]);
        split_f16x2(x3, Ah[k][3], Al[k][3]);
    }

    const int swz = (grp & 7) << 3;
#pragma unroll
    for (int n = 0; n < 8; n++) {
        uint2 b[4];
#pragma unroll
        for (int k = 0; k < 4; k++) b[k] = sB[n][k][lane];

        float c1[4] = {0.f, 0.f, 0.f, 0.f};
        float c2[4] = {0.f, 0.f, 0.f, 0.f};
#pragma unroll
        for (int k = 0; k < 4; k++) {
            mma_f16(c1, Ah[k], b[k].x, b[k].y);
            mma_f16(c2, Al[k], b[k].x, b[k].y);
        }

        int colw = (8 * n + 2 * tig) ^ swz;
        *reinterpret_cast<float2*>(&sEf[warp][grp][colw]) =
            make_float2(c1[0] + c2[0], c1[1] + c2[1]);
        *reinterpret_cast<float2*>(&sEf[warp][grp + 8][colw]) =
            make_float2(c1[2] + c2[2], c1[3] + c2[3]);
    }
    __syncwarp();

    int s2, d2;
    uint2 kk2, qq2;
    float4 vv1;
#pragma unroll
    for (int it = 0; it < 8; it++) {
        if (it < 7)
            vv1 = __ldg(reinterpret_cast<const float4*>(&g_V[(long)s1 * D + 4 * g]));
        if (it < 6) {
            s2 = __shfl_sync(0xFFFFFFFFu, sd, (it + 2) * 2 + half);
            d2 = __shfl_sync(0xFFFFFFFFu, sd, 16 + (it + 2) * 2 + half);
            kk2 = *reinterpret_cast<const uint2*>(&g_Kh[(long)s2 * 32 + 2 * g]);
            qq2 = *reinterpret_cast<const uint2*>(&g_Qh[(long)d2 * 32 + 2 * g]);
        }

        int r = it * 2 + half;
        float4 ef = *reinterpret_cast<const float4*>(
            &sEf[warp][r][(4 * g) ^ ((r & 7) << 3)]);

        float2 kA = h2f(kk0.x), kB = h2f(kk0.y);
        float2 qA = h2f(qq0.x), qB = h2f(qq0.y);

        float p = (kA.x * qA.x) * ef.x;
        p = fmaf(kA.y * qA.y, ef.y, p);
        p = fmaf(kB.x * qB.x, ef.z, p);
        p = fmaf(kB.y * qB.y, ef.w, p);
        p += __shfl_xor_sync(0xFFFFFFFFu, p, 1);

        // clamp in p-domain (+-5*sqrt(8)); exp(x/sqrt8)=2^(x*log2e/sqrt8)
        float sv = fminf(14.142135623730951f, fmaxf(-14.142135623730951f, p));
        float sc = exp2f(sv * 0.51002501915290554f);

        red_add_v4(&out[(long)d0 * D + 4 * g],
                   vv0.x * sc, vv0.y * sc, vv0.z * sc, vv0.w * sc);
        if ((g & 1) == 0)
            atomicAdd(&g_Z[d0 * H + (g >> 1)], sc);

        kk0 = kk1; qq0 = qq1; vv0 = vv1; s0 = s1; d0 = d1;
        kk1 = kk2; qq1 = qq2; s1 = s2; d1 = d2;
    }
}

// ---------------------------------------------------------------------------
// K3: out = wV / (Z + 1e-6)   (one float4 per thread)
// ---------------------------------------------------------------------------
__global__ void div_kernel(float4* __restrict__ out4) {
    int i = blockIdx.x * blockDim.x + threadIdx.x;
    if (i >= (N_NODES * D) / 4) return;
    int n  = i >> 4;
    int c4 = i & 15;
    int h  = c4 >> 1;
    float r = 1.0f / (g_Z[n * H + h] + 1e-6f);
    float4 v = out4[i];
    v.x *= r; v.y *= r; v.z *= r; v.w *= r;
    out4[i] = v;
}

// ---------------------------------------------------------------------------
extern "C" void kernel_launch(void* const* d_in, const int* in_sizes, int n_in,
                              void* d_out, int out_size)
{
    const float* x   = (const float*)d_in[0];
    const float* ea  = (const float*)d_in[1];
    const float* WQ  = (const float*)d_in[2];
    const float* WK  = (const float*)d_in[3];
    const float* WV  = (const float*)d_in[4];
    const float* WE  = (const float*)d_in[5];
    const int*   ei  = (const int*)d_in[6];
    float* out = (float*)d_out;

    (void)in_sizes; (void)n_in; (void)out_size;

    proj_kernel<<<391, 256>>>(x, WQ, WK, WV, out);
    fused_edge_kernel<<<(NEDGES / 16 + 7) / 8, 256>>>(ea, WE, ei, out);
    div_kernel<<<(N_NODES * D / 4 + 255) / 256, 256>>>((float4*)out);
}